// round 1
// baseline (speedup 1.0000x reference)
#include <cuda_runtime.h>
#include <cuda_bf16.h>
#include <math.h>

// Problem constants
// x:   [2, 2048, 1024]
// ctx: [2, 2048, 768]
// Wq:  [1024, 1024], Wkv: [768, 2048], Wo: [1024, 1024]
// H=16, Dh=64, scale = 1/8

#define BATCH 2
#define SEQ_N 2048
#define SEQ_M 2048
#define CDIM 1024
#define CTXDIM 768
#define HEADS 16
#define DH 64

// Scratch (allocation-free rule: device globals)
__device__ float g_Q[BATCH * SEQ_N * CDIM];        // 16 MB  [b*N+n][C]
__device__ float g_KV[BATCH * SEQ_M * 2 * CDIM];   // 32 MB  [b*M+m][2C] (K cols 0..1023, V cols 1024..2047)
__device__ float g_AO[BATCH * SEQ_N * CDIM];       // 16 MB  [b*N+n][C]

// ---------------------------------------------------------------------------
// Register-blocked SGEMM: C[M,N] = A[M,K] @ B[K,N], all row-major fp32.
// 128x128 block tile, 16 K-tile, 256 threads, 8x8 per thread.
// Requires M%128==0, N%128==0, K%16==0 (true for all our shapes).
// ---------------------------------------------------------------------------
__global__ __launch_bounds__(256) void sgemm128(const float* __restrict__ A,
                                                const float* __restrict__ B,
                                                float* __restrict__ C,
                                                int M, int N, int K)
{
    __shared__ float As[16][128];   // transposed: As[k][m]
    __shared__ float Bs[16][128];   // Bs[k][n]

    const int tid = threadIdx.x;
    const int tx = tid & 15;        // 0..15 -> 8 cols each
    const int ty = tid >> 4;        // 0..15 -> 8 rows each
    const int bx = blockIdx.x;      // N tile
    const int by = blockIdx.y;      // M tile

    float acc[8][8];
#pragma unroll
    for (int i = 0; i < 8; i++)
#pragma unroll
        for (int j = 0; j < 8; j++) acc[i][j] = 0.0f;

    const float* Ag = A + (size_t)by * 128 * K;
    const float* Bg = B + (size_t)bx * 128;

    for (int k0 = 0; k0 < K; k0 += 16) {
        // Load A tile 128x16 (512 float4) and B tile 16x128 (512 float4)
#pragma unroll
        for (int i = 0; i < 2; i++) {
            int t = tid + i * 256;
            int r  = t >> 2;            // 0..127
            int ck = (t & 3) << 2;      // 0,4,8,12
            float4 av = *(const float4*)(Ag + (size_t)r * K + k0 + ck);
            As[ck + 0][r] = av.x;
            As[ck + 1][r] = av.y;
            As[ck + 2][r] = av.z;
            As[ck + 3][r] = av.w;
            int rk = t >> 5;            // 0..15
            int cn = (t & 31) << 2;     // 0..124
            *(float4*)(&Bs[rk][cn]) = *(const float4*)(Bg + (size_t)(k0 + rk) * N + cn);
        }
        __syncthreads();

#pragma unroll
        for (int k = 0; k < 16; k++) {
            float a[8], b[8];
            *(float4*)(a)     = *(const float4*)(&As[k][ty * 8]);
            *(float4*)(a + 4) = *(const float4*)(&As[k][ty * 8 + 4]);
            *(float4*)(b)     = *(const float4*)(&Bs[k][tx * 8]);
            *(float4*)(b + 4) = *(const float4*)(&Bs[k][tx * 8 + 4]);
#pragma unroll
            for (int i = 0; i < 8; i++)
#pragma unroll
                for (int j = 0; j < 8; j++)
                    acc[i][j] = fmaf(a[i], b[j], acc[i][j]);
        }
        __syncthreads();
    }

    float* Cg = C + (size_t)(by * 128 + ty * 8) * N + bx * 128 + tx * 8;
#pragma unroll
    for (int i = 0; i < 8; i++) {
        *(float4*)(Cg + (size_t)i * N)     = make_float4(acc[i][0], acc[i][1], acc[i][2], acc[i][3]);
        *(float4*)(Cg + (size_t)i * N + 4) = make_float4(acc[i][4], acc[i][5], acc[i][6], acc[i][7]);
    }
}

// ---------------------------------------------------------------------------
// Fused attention with online softmax.
// Grid: (B*H = 32, N/64 = 32). Block: 256 threads.
// Each CTA: one (b,h), 64 query rows; streams K/V in 64-row tiles.
// Thread (ty=tid/16, tx=tid%16): owns 4 query rows (ty*4..) and either
// 4 key cols (S phase) or 4 dh cols (PV phase) at tx*4..
// ---------------------------------------------------------------------------
__global__ __launch_bounds__(256) void attn64(const float* __restrict__ Q,
                                              const float* __restrict__ KV,
                                              float* __restrict__ O)
{
    extern __shared__ float sm[];
    float* Qs = sm;           // [d*64 + r]   (transposed) 4096 floats
    float* Ks = sm + 4096;    // [d*64 + c]   (transposed)
    float* Vs = sm + 8192;    // [k*64 + d]
    float* Ps = sm + 12288;   // [r*64 + c]

    const int tid = threadIdx.x;
    const int tx = tid & 15;
    const int ty = tid >> 4;
    const int bh = blockIdx.x;
    const int b = bh >> 4;
    const int h = bh & 15;
    const int n0 = blockIdx.y * 64;

    const float* Qg = Q + ((size_t)(b * SEQ_N + n0)) * CDIM + h * DH;
    const float* Kg = KV + ((size_t)b * SEQ_M) * (2 * CDIM) + h * DH;
    const float* Vg = Kg + CDIM;

    // Load Q tile (64 rows x 64 dh), transposed into Qs[d][r]
#pragma unroll
    for (int i = 0; i < 4; i++) {
        int t = tid + i * 256;
        int r = t >> 4;             // 0..63
        int dc = (t & 15) << 2;     // 0..60
        float4 qv = *(const float4*)(Qg + (size_t)r * CDIM + dc);
        Qs[(dc + 0) * 64 + r] = qv.x;
        Qs[(dc + 1) * 64 + r] = qv.y;
        Qs[(dc + 2) * 64 + r] = qv.z;
        Qs[(dc + 3) * 64 + r] = qv.w;
    }

    float m_run[4], l_run[4], o[4][4];
#pragma unroll
    for (int i = 0; i < 4; i++) {
        m_run[i] = -1e30f;
        l_run[i] = 0.0f;
#pragma unroll
        for (int j = 0; j < 4; j++) o[i][j] = 0.0f;
    }

    for (int m0 = 0; m0 < SEQ_M; m0 += 64) {
        // Load K (transposed) and V (direct) tiles
#pragma unroll
        for (int i = 0; i < 4; i++) {
            int t = tid + i * 256;
            int r = t >> 4;
            int dc = (t & 15) << 2;
            float4 kv = *(const float4*)(Kg + (size_t)(m0 + r) * (2 * CDIM) + dc);
            Ks[(dc + 0) * 64 + r] = kv.x;
            Ks[(dc + 1) * 64 + r] = kv.y;
            Ks[(dc + 2) * 64 + r] = kv.z;
            Ks[(dc + 3) * 64 + r] = kv.w;
            float4 vv = *(const float4*)(Vg + (size_t)(m0 + r) * (2 * CDIM) + dc);
            *(float4*)(&Vs[r * 64 + dc]) = vv;
        }
        __syncthreads();

        // S = Q @ K^T  (4x4 per thread)
        float s[4][4];
#pragma unroll
        for (int i = 0; i < 4; i++)
#pragma unroll
            for (int j = 0; j < 4; j++) s[i][j] = 0.0f;

#pragma unroll
        for (int d = 0; d < 64; d++) {
            float4 qv = *(const float4*)(&Qs[d * 64 + ty * 4]);
            float4 kv = *(const float4*)(&Ks[d * 64 + tx * 4]);
            float qa[4] = {qv.x, qv.y, qv.z, qv.w};
            float ka[4] = {kv.x, kv.y, kv.z, kv.w};
#pragma unroll
            for (int i = 0; i < 4; i++)
#pragma unroll
                for (int j = 0; j < 4; j++)
                    s[i][j] = fmaf(qa[i], ka[j], s[i][j]);
        }

        // Online softmax update per query row
#pragma unroll
        for (int i = 0; i < 4; i++) {
#pragma unroll
            for (int j = 0; j < 4; j++) s[i][j] *= 0.125f;  // Dh^-0.5

            float rm = fmaxf(fmaxf(s[i][0], s[i][1]), fmaxf(s[i][2], s[i][3]));
#pragma unroll
            for (int off = 8; off >= 1; off >>= 1)
                rm = fmaxf(rm, __shfl_xor_sync(0xffffffffu, rm, off));

            float mn = fmaxf(m_run[i], rm);
            float corr = __expf(m_run[i] - mn);
            float p[4];
            float rs = 0.0f;
#pragma unroll
            for (int j = 0; j < 4; j++) {
                p[j] = __expf(s[i][j] - mn);
                rs += p[j];
            }
#pragma unroll
            for (int off = 8; off >= 1; off >>= 1)
                rs += __shfl_xor_sync(0xffffffffu, rs, off);

            l_run[i] = l_run[i] * corr + rs;
            m_run[i] = mn;
#pragma unroll
            for (int j = 0; j < 4; j++) o[i][j] *= corr;

            *(float4*)(&Ps[(ty * 4 + i) * 64 + tx * 4]) = make_float4(p[0], p[1], p[2], p[3]);
        }
        __syncthreads();

        // O += P @ V   (thread now owns dh cols tx*4..tx*4+3)
#pragma unroll
        for (int k = 0; k < 64; k++) {
            float4 vv = *(const float4*)(&Vs[k * 64 + tx * 4]);
#pragma unroll
            for (int i = 0; i < 4; i++) {
                float pv = Ps[(ty * 4 + i) * 64 + k];
                o[i][0] = fmaf(pv, vv.x, o[i][0]);
                o[i][1] = fmaf(pv, vv.y, o[i][1]);
                o[i][2] = fmaf(pv, vv.z, o[i][2]);
                o[i][3] = fmaf(pv, vv.w, o[i][3]);
            }
        }
        __syncthreads();
    }

    // Normalize and write [b*N + n][h*64 + d]
    float* Og = O + ((size_t)(b * SEQ_N + n0 + ty * 4)) * CDIM + h * DH + tx * 4;
#pragma unroll
    for (int i = 0; i < 4; i++) {
        float inv = 1.0f / l_run[i];
        *(float4*)(Og + (size_t)i * CDIM) =
            make_float4(o[i][0] * inv, o[i][1] * inv, o[i][2] * inv, o[i][3] * inv);
    }
}

// ---------------------------------------------------------------------------
extern "C" void kernel_launch(void* const* d_in, const int* in_sizes, int n_in,
                              void* d_out, int out_size)
{
    const float* x   = (const float*)d_in[0];
    const float* ctx = (const float*)d_in[1];
    const float* Wq  = (const float*)d_in[2];
    const float* Wkv = (const float*)d_in[3];
    const float* Wo  = (const float*)d_in[4];
    float* out = (float*)d_out;

    float *Qb, *KVb, *AOb;
    cudaGetSymbolAddress((void**)&Qb,  g_Q);
    cudaGetSymbolAddress((void**)&KVb, g_KV);
    cudaGetSymbolAddress((void**)&AOb, g_AO);

    // Q = x @ Wq : [4096,1024] = [4096,1024]x[1024,1024]
    sgemm128<<<dim3(CDIM / 128, (BATCH * SEQ_N) / 128), 256>>>(
        x, Wq, Qb, BATCH * SEQ_N, CDIM, CDIM);

    // KV = ctx @ Wkv : [4096,2048] = [4096,768]x[768,2048]
    sgemm128<<<dim3((2 * CDIM) / 128, (BATCH * SEQ_M) / 128), 256>>>(
        ctx, Wkv, KVb, BATCH * SEQ_M, 2 * CDIM, CTXDIM);

    // Fused attention
    cudaFuncSetAttribute(attn64, cudaFuncAttributeMaxDynamicSharedMemorySize, 65536);
    attn64<<<dim3(BATCH * HEADS, SEQ_N / 64), 256, 65536>>>(Qb, KVb, AOb);

    // out = AO @ Wo
    sgemm128<<<dim3(CDIM / 128, (BATCH * SEQ_N) / 128), 256>>>(
        AOb, Wo, out, BATCH * SEQ_N, CDIM, CDIM);
}

// round 3
// speedup vs baseline: 2.9656x; 2.9656x over previous
#include <cuda_runtime.h>
#include <cuda_bf16.h>
#include <cstdint>
#include <math.h>

// x: [2,2048,1024], ctx: [2,2048,768], Wq: [1024,1024], Wkv: [768,2048], Wo: [1024,1024]
#define BATCH 2
#define SEQ_N 2048
#define SEQ_M 2048
#define CDIM 1024
#define CTXDIM 768
#define HEADS 16
#define DH 64

// ---------------- device scratch (allocation-free rule) ----------------
__device__ float g_Q [BATCH * SEQ_N * CDIM];
__device__ float g_KV[BATCH * SEQ_M * 2 * CDIM];
__device__ float g_AO[BATCH * SEQ_N * CDIM];
__device__ float g_Xr[BATCH * SEQ_N * CDIM];
__device__ float g_Cr[BATCH * SEQ_M * CTXDIM];
__device__ float g_WqT [CDIM * CDIM];
__device__ float g_WkvT[2 * CDIM * CTXDIM];
__device__ float g_WoT [CDIM * CDIM];

// ---------------- helpers ----------------
__device__ __forceinline__ float rna_tf32(float x) {
    float r;
    asm("cvt.rna.tf32.f32 %0, %1;" : "=f"(r) : "f"(x));
    return r;
}
__device__ __forceinline__ float exp2_fast(float x) {
    float r;
    asm("ex2.approx.ftz.f32 %0, %1;" : "=f"(r) : "f"(x));
    return r;
}
// D += A @ B  (m16n8k8, tf32 in, f32 acc)
__device__ __forceinline__ void mma_tf32(float* d, const uint32_t* a, const uint32_t* b) {
    asm volatile(
        "mma.sync.aligned.m16n8k8.row.col.f32.tf32.tf32.f32 "
        "{%0,%1,%2,%3}, {%4,%5,%6,%7}, {%8,%9}, {%0,%1,%2,%3};"
        : "+f"(d[0]), "+f"(d[1]), "+f"(d[2]), "+f"(d[3])
        : "r"(a[0]), "r"(a[1]), "r"(a[2]), "r"(a[3]), "r"(b[0]), "r"(b[1]));
}

// ---------------- prep kernels ----------------
__global__ void round_tf32_k(const float4* __restrict__ in, float4* __restrict__ out, int n4) {
    int i = blockIdx.x * blockDim.x + threadIdx.x;
    if (i < n4) {
        float4 v = in[i];
        out[i] = make_float4(rna_tf32(v.x), rna_tf32(v.y), rna_tf32(v.z), rna_tf32(v.w));
    }
}
// out[n][k] = rna(in[k][n]); in is [K,N] row-major
__global__ void transpose_rna_k(const float* __restrict__ in, float* __restrict__ out, int K, int N) {
    __shared__ float t[32][33];
    int n0 = blockIdx.x * 32, k0 = blockIdx.y * 32;
    int x = threadIdx.x, y = threadIdx.y;
#pragma unroll
    for (int i = 0; i < 32; i += 8)
        t[y + i][x] = in[(size_t)(k0 + y + i) * N + n0 + x];
    __syncthreads();
#pragma unroll
    for (int i = 0; i < 32; i += 8)
        out[(size_t)(n0 + y + i) * K + k0 + x] = rna_tf32(t[x][y + i]);
}

// ---------------- tf32 mma GEMM: C[M,N] = A[M,K] @ BT[N,K]^T ----------------
// 128x128 tile, BK=16, 256 threads (8 warps: 4 in M x 2 in N, warp = 32x64).
// Smem rows padded to 20 floats -> conflict-free fragment loads.
template <int RNA>
__global__ __launch_bounds__(256) void gemm_mma(const float* __restrict__ A,
                                                const float* __restrict__ BT,
                                                float* __restrict__ C,
                                                int M, int N, int K)
{
    __shared__ float As[2][128 * 20];
    __shared__ float Bs[2][128 * 20];
    const int tid = threadIdx.x, lane = tid & 31, wid = tid >> 5;
    const int wm = (wid & 3) * 32, wn = (wid >> 2) * 64;
    const int bx = blockIdx.x * 128, by = blockIdx.y * 128;

    const float* Ag = A  + (size_t)by * K;
    const float* Bg = BT + (size_t)bx * K;

    float acc[2][8][4];
#pragma unroll
    for (int mi = 0; mi < 2; mi++)
#pragma unroll
        for (int j = 0; j < 8; j++)
#pragma unroll
            for (int q = 0; q < 4; q++) acc[mi][j][q] = 0.0f;

    float4 ra[2], rb[2];
#pragma unroll
    for (int i = 0; i < 2; i++) {
        int idx = tid + i * 256, r = idx >> 2, c = (idx & 3) * 4;
        ra[i] = *(const float4*)(Ag + (size_t)r * K + c);
        rb[i] = *(const float4*)(Bg + (size_t)r * K + c);
    }
#pragma unroll
    for (int i = 0; i < 2; i++) {
        int idx = tid + i * 256, r = idx >> 2, c = (idx & 3) * 4;
        *(float4*)&As[0][r * 20 + c] = ra[i];
        *(float4*)&Bs[0][r * 20 + c] = rb[i];
    }
    __syncthreads();

    const int nk = K >> 4;
    for (int kt = 0; kt < nk; kt++) {
        const int buf = kt & 1;
        if (kt + 1 < nk) {
            const float* Agn = Ag + (size_t)(kt + 1) * 16;
            const float* Bgn = Bg + (size_t)(kt + 1) * 16;
#pragma unroll
            for (int i = 0; i < 2; i++) {
                int idx = tid + i * 256, r = idx >> 2, c = (idx & 3) * 4;
                ra[i] = *(const float4*)(Agn + (size_t)r * K + c);
                rb[i] = *(const float4*)(Bgn + (size_t)r * K + c);
            }
        }
#pragma unroll
        for (int s = 0; s < 2; s++) {
            const int k0 = s * 8;
            uint32_t af[2][4], bf[8][2];
#pragma unroll
            for (int mi = 0; mi < 2; mi++) {
                int rr = wm + mi * 16 + (lane >> 2);
                af[mi][0] = __float_as_uint(As[buf][rr * 20 + k0 + (lane & 3)]);
                af[mi][1] = __float_as_uint(As[buf][(rr + 8) * 20 + k0 + (lane & 3)]);
                af[mi][2] = __float_as_uint(As[buf][rr * 20 + k0 + (lane & 3) + 4]);
                af[mi][3] = __float_as_uint(As[buf][(rr + 8) * 20 + k0 + (lane & 3) + 4]);
            }
#pragma unroll
            for (int j = 0; j < 8; j++) {
                int nb = wn + j * 8 + (lane >> 2);
                bf[j][0] = __float_as_uint(Bs[buf][nb * 20 + k0 + (lane & 3)]);
                bf[j][1] = __float_as_uint(Bs[buf][nb * 20 + k0 + (lane & 3) + 4]);
            }
#pragma unroll
            for (int mi = 0; mi < 2; mi++)
#pragma unroll
                for (int j = 0; j < 8; j++)
                    mma_tf32(acc[mi][j], af[mi], bf[j]);
        }
        if (kt + 1 < nk) {
            __syncthreads();
            const int nb2 = (kt + 1) & 1;
#pragma unroll
            for (int i = 0; i < 2; i++) {
                int idx = tid + i * 256, r = idx >> 2, c = (idx & 3) * 4;
                *(float4*)&As[nb2][r * 20 + c] = ra[i];
                *(float4*)&Bs[nb2][r * 20 + c] = rb[i];
            }
            __syncthreads();
        }
    }

#pragma unroll
    for (int mi = 0; mi < 2; mi++) {
        int r0 = by + wm + mi * 16 + (lane >> 2);
#pragma unroll
        for (int j = 0; j < 8; j++) {
            int col = bx + wn + j * 8 + 2 * (lane & 3);
            float2 v0, v1;
            if (RNA) {
                v0 = make_float2(rna_tf32(acc[mi][j][0]), rna_tf32(acc[mi][j][1]));
                v1 = make_float2(rna_tf32(acc[mi][j][2]), rna_tf32(acc[mi][j][3]));
            } else {
                v0 = make_float2(acc[mi][j][0], acc[mi][j][1]);
                v1 = make_float2(acc[mi][j][2], acc[mi][j][3]);
            }
            *(float2*)(C + (size_t)r0 * N + col)       = v0;
            *(float2*)(C + (size_t)(r0 + 8) * N + col) = v1;
        }
    }
}

// ---------------- FlashAttention-2 with tf32 mma ----------------
// Grid (B*H=32, N/64=32), 128 threads (4 warps; warp = 16 query rows).
// Smem: Qs[64][68], Ks[64][68], Vs[64][72], Ps[4][16][68]. ~70.6 KB.
static constexpr int QS_OFF = 0;
static constexpr int KS_OFF = 64 * 68;
static constexpr int VS_OFF = 2 * 64 * 68;
static constexpr int PS_OFF = 2 * 64 * 68 + 64 * 72;
static constexpr int ATTN_SMEM = (PS_OFF + 4 * 16 * 68) * 4;  // bytes

__global__ __launch_bounds__(128) void attn_mma(const float* __restrict__ Q,
                                                const float* __restrict__ KV,
                                                float* __restrict__ O)
{
    extern __shared__ float smf[];
    float* Qs = smf + QS_OFF;
    float* Ks = smf + KS_OFF;
    float* Vs = smf + VS_OFF;

    const int tid = threadIdx.x, lane = tid & 31, wid = tid >> 5;
    const int b = blockIdx.x >> 4, h = blockIdx.x & 15;
    const int n0 = blockIdx.y * 64;

    const float* Qg = Q  + ((size_t)(b * SEQ_N + n0)) * CDIM + h * DH;
    const float* Kg = KV + (size_t)b * SEQ_M * (2 * CDIM) + h * DH;
    const float* Vg = Kg + CDIM;

    float* Pw = smf + PS_OFF + wid * (16 * 68);

    // load Q tile (64x64)
#pragma unroll
    for (int i = 0; i < 8; i++) {
        int idx = tid + i * 128, r = idx >> 4, c = (idx & 15) * 4;
        *(float4*)&Qs[r * 68 + c] = *(const float4*)(Qg + (size_t)r * CDIM + c);
    }

    const float SCALE = 0.125f * 1.4426950408889634f;  // Dh^-0.5 * log2(e)
    float m0r = -1e30f, m1r = -1e30f, l0 = 0.0f, l1 = 0.0f;
    float oacc[8][4];
#pragma unroll
    for (int j = 0; j < 8; j++)
#pragma unroll
        for (int q = 0; q < 4; q++) oacc[j][q] = 0.0f;

    const int r_ = lane >> 2, kq = lane & 3;

    for (int mt = 0; mt < SEQ_M; mt += 64) {
        __syncthreads();  // previous S/PV done with Ks/Vs (and Q stores before 1st mma)
#pragma unroll
        for (int i = 0; i < 8; i++) {
            int idx = tid + i * 128, r = idx >> 4, c = (idx & 15) * 4;
            *(float4*)&Ks[r * 68 + c] = *(const float4*)(Kg + (size_t)(mt + r) * (2 * CDIM) + c);
            *(float4*)&Vs[r * 72 + c] = *(const float4*)(Vg + (size_t)(mt + r) * (2 * CDIM) + c);
        }
        __syncthreads();

        // S = Q @ K^T  (warp: 16 x 64)
        float sacc[8][4];
#pragma unroll
        for (int j = 0; j < 8; j++)
#pragma unroll
            for (int q = 0; q < 4; q++) sacc[j][q] = 0.0f;

#pragma unroll
        for (int s = 0; s < 8; s++) {
            const int k0 = s * 8;
            uint32_t af[4];
            int rr = wid * 16 + r_;
            af[0] = __float_as_uint(Qs[rr * 68 + k0 + kq]);
            af[1] = __float_as_uint(Qs[(rr + 8) * 68 + k0 + kq]);
            af[2] = __float_as_uint(Qs[rr * 68 + k0 + kq + 4]);
            af[3] = __float_as_uint(Qs[(rr + 8) * 68 + k0 + kq + 4]);
#pragma unroll
            for (int j = 0; j < 8; j++) {
                uint32_t bf[2];
                int nb = j * 8 + r_;
                bf[0] = __float_as_uint(Ks[nb * 68 + k0 + kq]);
                bf[1] = __float_as_uint(Ks[nb * 68 + k0 + kq + 4]);
                mma_tf32(sacc[j], af, bf);
            }
        }

        // online softmax (log2 domain); thread owns rows r_ and r_+8 of warp tile
        float rm0 = -1e30f, rm1 = -1e30f;
#pragma unroll
        for (int j = 0; j < 8; j++) {
            rm0 = fmaxf(rm0, fmaxf(sacc[j][0], sacc[j][1]));
            rm1 = fmaxf(rm1, fmaxf(sacc[j][2], sacc[j][3]));
        }
        rm0 = fmaxf(rm0, __shfl_xor_sync(0xffffffffu, rm0, 1));
        rm0 = fmaxf(rm0, __shfl_xor_sync(0xffffffffu, rm0, 2));
        rm1 = fmaxf(rm1, __shfl_xor_sync(0xffffffffu, rm1, 1));
        rm1 = fmaxf(rm1, __shfl_xor_sync(0xffffffffu, rm1, 2));
        rm0 *= SCALE; rm1 *= SCALE;
        float mn0 = fmaxf(m0r, rm0), mn1 = fmaxf(m1r, rm1);
        float c0 = exp2_fast(m0r - mn0), c1 = exp2_fast(m1r - mn1);
        m0r = mn0; m1r = mn1;

        float rs0 = 0.0f, rs1 = 0.0f;
#pragma unroll
        for (int j = 0; j < 8; j++) {
            float p00 = rna_tf32(exp2_fast(fmaf(sacc[j][0], SCALE, -mn0)));
            float p01 = rna_tf32(exp2_fast(fmaf(sacc[j][1], SCALE, -mn0)));
            float p10 = rna_tf32(exp2_fast(fmaf(sacc[j][2], SCALE, -mn1)));
            float p11 = rna_tf32(exp2_fast(fmaf(sacc[j][3], SCALE, -mn1)));
            rs0 += p00 + p01;
            rs1 += p10 + p11;
            int col = j * 8 + 2 * kq;
            Pw[r_ * 68 + col]           = p00;
            Pw[r_ * 68 + col + 1]       = p01;
            Pw[(r_ + 8) * 68 + col]     = p10;
            Pw[(r_ + 8) * 68 + col + 1] = p11;
        }
        rs0 += __shfl_xor_sync(0xffffffffu, rs0, 1);
        rs0 += __shfl_xor_sync(0xffffffffu, rs0, 2);
        rs1 += __shfl_xor_sync(0xffffffffu, rs1, 1);
        rs1 += __shfl_xor_sync(0xffffffffu, rs1, 2);
        l0 = l0 * c0 + rs0;
        l1 = l1 * c1 + rs1;
#pragma unroll
        for (int j = 0; j < 8; j++) {
            oacc[j][0] *= c0; oacc[j][1] *= c0;
            oacc[j][2] *= c1; oacc[j][3] *= c1;
        }
        __syncwarp();

        // O += P @ V  (A = Pw from smem, B = Vs)
#pragma unroll
        for (int s = 0; s < 8; s++) {
            const int k0 = s * 8;
            uint32_t af[4];
            af[0] = __float_as_uint(Pw[r_ * 68 + k0 + kq]);
            af[1] = __float_as_uint(Pw[(r_ + 8) * 68 + k0 + kq]);
            af[2] = __float_as_uint(Pw[r_ * 68 + k0 + kq + 4]);
            af[3] = __float_as_uint(Pw[(r_ + 8) * 68 + k0 + kq + 4]);
#pragma unroll
            for (int j = 0; j < 8; j++) {
                uint32_t bf[2];
                bf[0] = __float_as_uint(Vs[(k0 + kq) * 72 + j * 8 + r_]);
                bf[1] = __float_as_uint(Vs[(k0 + kq + 4) * 72 + j * 8 + r_]);
                mma_tf32(oacc[j], af, bf);
            }
        }
    }

    // epilogue: normalize, rna-round, store
    float inv0 = 1.0f / l0, inv1 = 1.0f / l1;
    int row = n0 + wid * 16 + r_;
    float* Ob = O + ((size_t)(b * SEQ_N + row)) * CDIM + h * DH;
#pragma unroll
    for (int j = 0; j < 8; j++) {
        int col = j * 8 + 2 * kq;
        *(float2*)(Ob + col) =
            make_float2(rna_tf32(oacc[j][0] * inv0), rna_tf32(oacc[j][1] * inv0));
        *(float2*)(Ob + (size_t)8 * CDIM + col) =
            make_float2(rna_tf32(oacc[j][2] * inv1), rna_tf32(oacc[j][3] * inv1));
    }
}

// ---------------------------------------------------------------------------
extern "C" void kernel_launch(void* const* d_in, const int* in_sizes, int n_in,
                              void* d_out, int out_size)
{
    const float* x   = (const float*)d_in[0];
    const float* ctx = (const float*)d_in[1];
    const float* Wq  = (const float*)d_in[2];
    const float* Wkv = (const float*)d_in[3];
    const float* Wo  = (const float*)d_in[4];
    float* out = (float*)d_out;

    float *Qb, *KVb, *AOb, *Xr, *Cr, *WqT, *WkvT, *WoT;
    cudaGetSymbolAddress((void**)&Qb,   g_Q);
    cudaGetSymbolAddress((void**)&KVb,  g_KV);
    cudaGetSymbolAddress((void**)&AOb,  g_AO);
    cudaGetSymbolAddress((void**)&Xr,   g_Xr);
    cudaGetSymbolAddress((void**)&Cr,   g_Cr);
    cudaGetSymbolAddress((void**)&WqT,  g_WqT);
    cudaGetSymbolAddress((void**)&WkvT, g_WkvT);
    cudaGetSymbolAddress((void**)&WoT,  g_WoT);

    // tf32 pre-rounding + weight transposes to [N,K]
    {
        int n4 = BATCH * SEQ_N * CDIM / 4;
        round_tf32_k<<<(n4 + 255) / 256, 256>>>((const float4*)x, (float4*)Xr, n4);
        n4 = BATCH * SEQ_M * CTXDIM / 4;
        round_tf32_k<<<(n4 + 255) / 256, 256>>>((const float4*)ctx, (float4*)Cr, n4);
        transpose_rna_k<<<dim3(CDIM / 32, CDIM / 32), dim3(32, 8)>>>(Wq, WqT, CDIM, CDIM);
        transpose_rna_k<<<dim3(2 * CDIM / 32, CTXDIM / 32), dim3(32, 8)>>>(Wkv, WkvT, CTXDIM, 2 * CDIM);
        transpose_rna_k<<<dim3(CDIM / 32, CDIM / 32), dim3(32, 8)>>>(Wo, WoT, CDIM, CDIM);
    }

    // Q = x @ Wq (rna-rounded output: S-mma operand)
    gemm_mma<1><<<dim3(CDIM / 128, BATCH * SEQ_N / 128), 256>>>(
        Xr, WqT, Qb, BATCH * SEQ_N, CDIM, CDIM);
    // KV = ctx @ Wkv (rna-rounded: K,V are mma operands)
    gemm_mma<1><<<dim3(2 * CDIM / 128, BATCH * SEQ_M / 128), 256>>>(
        Cr, WkvT, KVb, BATCH * SEQ_M, 2 * CDIM, CTXDIM);

    // fused flash attention (tf32 mma)
    cudaFuncSetAttribute(attn_mma, cudaFuncAttributeMaxDynamicSharedMemorySize, ATTN_SMEM);
    attn_mma<<<dim3(BATCH * HEADS, SEQ_N / 64), 128, ATTN_SMEM>>>(Qb, KVb, AOb);

    // out = AO @ Wo (no rounding on final output)
    gemm_mma<0><<<dim3(CDIM / 128, BATCH * SEQ_N / 128), 256>>>(
        AOb, WoT, out, BATCH * SEQ_N, CDIM, CDIM);
}